// round 3
// baseline (speedup 1.0000x reference)
#include <cuda_runtime.h>

// Problem constants (match reference_code)
#define VDEPTH   10000
#define ND       13
#define NS       26
#define NFIELD   39          // ND + NS
#define NK       8
#define ELEMS    (NFIELD * NK)   // 312 floats per v-row

// One CTA per batch row. 320 threads (10 full warps).
// Thread t < 312 owns field_f element (f = t/8, k = t%8).
__global__ __launch_bounds__(320, 6)
void ffm_kernel(const float* __restrict__ dense,
                const int*   __restrict__ sparse,
                const float* __restrict__ w0,
                const float* __restrict__ w,
                const float* __restrict__ v,
                float*       __restrict__ out)
{
    const int b = blockIdx.x;
    const int t = threadIdx.x;

    __shared__ float s_dense[ND];
    __shared__ int   s_idx[NS];
    __shared__ float sh[ELEMS];
    __shared__ float red[2];       // red[0] = linear accum (init w0), red[1] = sum(acc^2)

    if (t < ND)                s_dense[t]      = dense[b * ND + t];
    if (t >= 32 && t < 32+NS)  s_idx[t - 32]   = sparse[b * NS + (t - 32)] + ND + (t - 32) * VDEPTH;
    if (t == 64)               red[0] = w0[0];
    if (t == 65)               red[1] = 0.0f;
    __syncthreads();

    // ---- field_f accumulation: dense part (L2-resident) + 26 DRAM gathers ----
    float acc = 0.0f;
    if (t < ELEMS) {
        const float* vp = v + t;
        #pragma unroll
        for (int d = 0; d < ND; d++)
            acc = fmaf(s_dense[d], __ldg(vp + d * ELEMS), acc);
        #pragma unroll
        for (int j = 0; j < NS; j++)
            acc += __ldg(vp + s_idx[j] * ELEMS);   // offset < 2^27, int math is safe
        sh[t] = acc;
    }

    // ---- sum of squares over all 312 elements (warp shuffle + shared atomic) ----
    float q = acc * acc;   // threads >= 312 contribute 0
    #pragma unroll
    for (int o = 16; o; o >>= 1) q += __shfl_xor_sync(0xffffffffu, q, o);
    if ((t & 31) == 0) atomicAdd(&red[1], q);

    // ---- linear term: warp0 gathers w[idx], warp1 does dense dot w[:13] ----
    float lp = 0.0f;
    if (t < NS)                     lp = __ldg(w + s_idx[t]);
    else if (t >= 32 && t < 32+ND)  lp = s_dense[t - 32] * __ldg(w + (t - 32));
    #pragma unroll
    for (int o = 16; o; o >>= 1) lp += __shfl_xor_sync(0xffffffffu, lp, o);
    if ((t == 0) || (t == 32)) atomicAdd(&red[0], lp);

    __syncthreads();

    // ---- S[k] = sum_f field_f[f,k];  out = lin + 0.5*(||S||^2 - q) ----
    if (t < NK) {
        float s = 0.0f;
        #pragma unroll
        for (int f = 0; f < NFIELD; f++) s += sh[f * NK + t];
        float ss = s * s;
        #pragma unroll
        for (int o = 4; o; o >>= 1) ss += __shfl_xor_sync(0xffu, ss, o);
        if (t == 0)
            out[b] = red[0] + 0.5f * (ss - red[1]);
    }
}

extern "C" void kernel_launch(void* const* d_in, const int* in_sizes, int n_in,
                              void* d_out, int out_size)
{
    const float* dense  = (const float*)d_in[0];   // [B, 13]
    const int*   sparse = (const int*)  d_in[1];   // [B, 26]
    const float* w0     = (const float*)d_in[2];   // [1]
    const float* w      = (const float*)d_in[3];   // [260013, 1]
    const float* v      = (const float*)d_in[4];   // [260013, 39, 8]
    float* out          = (float*)d_out;           // [B, 1]

    const int batch = in_sizes[0] / ND;
    ffm_kernel<<<batch, 320>>>(dense, sparse, w0, w, v, out);
}